// round 16
// baseline (speedup 1.0000x reference)
#include <cuda_runtime.h>
#include <cstdint>

// Problem constants
#define BATCH 2
#define NPTS  8192
#define RQ    2048
#define KN    16     // neighbors kept
#define BR    4096   // BATCH*RQ groups
#define CINF  64
#define COUTF 128
#define K2F   256
#define GPB   16     // groups per block in stage B
#define TPB   512    // threads per block in stage B
#define WPQ   8      // warps per query in stage A
#define CPW   1024   // candidates per warp

// Scratch: neighbor indices for the 4096 rep groups
__device__ int g_knn[BR * KN];

__device__ __forceinline__ unsigned fkey(float f) {
    unsigned u = __float_as_uint(f);
    return (u & 0x80000000u) ? ~u : (u | 0x80000000u);
}

__device__ __forceinline__ unsigned long long
warp_min_u64(unsigned long long v) {
#pragma unroll
    for (int o = 16; o > 0; o >>= 1) {
        unsigned long long other = __shfl_xor_sync(0xffffffffu, v, o);
        if (other < v) v = other;
    }
    return v;
}

// ---------------------------------------------------------------------------
// Stage A: exact KNN, warp-autonomous tournament. Block = 512 thr = 16 warps
// = 2 queries x 8 warps; each warp owns 1024 candidates, keys in 32 regs.
// d2 arithmetic bit-identical to the passing kernels: dot = FMA chain,
// sq = plain mul+add, combine unfused; key = order-mapped fkey(d2).
// Each warp extracts its sorted top-17 (u64 key = fkey<<32 | idx -> exact
// jax top_k tie-break) with shfl-only rounds: NO block barriers, NO atomics.
// Winner lane erases its register slot (predicated unrolled) and recomputes
// its head. Then one warp per query merges the 8 sorted lists, drops entry 0
// (the self point, as reference drops idx[...,0]), writes g_knn.
// ---------------------------------------------------------------------------
__global__ void __launch_bounds__(512, 2) knn_kernel(
    const float* __restrict__ points, const int* __restrict__ rep_idx)
{
    __shared__ unsigned long long lists[2][WPQ][KN + 1];

    int tid  = threadIdx.x;
    int wid  = tid >> 5;
    int lane = tid & 31;
    int s    = wid >> 3;           // query slot within block (0/1)
    int part = wid & 7;            // candidate partition (1024 each)
    int g0   = blockIdx.x * 2;
    int gq   = g0 + s;
    int b    = g0 >> 11;           // both queries share the batch
    int j0   = part * CPW;

    {
        int r  = gq & (RQ - 1);
        int ri = rep_idx[r];
        const float* qp = points + ((size_t)b * NPTS + ri) * 3;
        float qx = qp[0], qy = qp[1], qz = qp[2];
        float qs = __fadd_rn(__fadd_rn(__fmul_rn(qx, qx), __fmul_rn(qy, qy)),
                             __fmul_rn(qz, qz));

        // distance phase: 32 candidates per lane, keys in registers
        unsigned keys[32];
#pragma unroll
        for (int c = 0; c < 32; ++c) {
            int j = j0 + c * 32 + lane;
            const float* pp = points + ((size_t)b * NPTS + j) * 3;
            float x = pp[0], y = pp[1], z = pp[2];
            float sj = __fadd_rn(__fadd_rn(__fmul_rn(x, x), __fmul_rn(y, y)),
                                 __fmul_rn(z, z));
            float dot = __fmaf_rn(qz, z, __fmaf_rn(qy, y, __fmul_rn(qx, x)));
            float d2 = __fsub_rn(__fadd_rn(qs, sj), __fmul_rn(2.0f, dot));
            keys[c] = fkey(d2);
        }

        // local head = min (key, idx) over this lane's 32 slots
        auto localmin = [&]() -> unsigned long long {
            unsigned kmin = keys[0];
#pragma unroll
            for (int c = 1; c < 32; ++c) kmin = min(kmin, keys[c]);
            int mc = 31;
#pragma unroll
            for (int c = 30; c >= 0; --c) if (keys[c] == kmin) mc = c;
            return ((unsigned long long)kmin << 32) |
                   (unsigned)(j0 + mc * 32 + lane);
        };

        unsigned long long head = localmin();

        // 17 warp-local extraction rounds (no barriers, no atomics)
        for (int it = 0; it <= KN; ++it) {
            unsigned long long w = warp_min_u64(head);
            if (lane == 0) lists[s][part][it] = w;
            if (head == w) {                 // this lane owned the winner
                int mc = (int)(((unsigned)w - (unsigned)j0) >> 5);
#pragma unroll
                for (int c = 0; c < 32; ++c) if (c == mc) keys[c] = ~0u;
                head = localmin();
            }
        }
    }
    __syncthreads();

    // merge: warp 0 -> query 0, warp 1 -> query 1. 8 sorted lists of 17.
    if (wid < 2) {
        int q = wid;
        int pos = 0;                          // per-lane cursor (lanes 0..7)
        for (int r2 = 0; r2 <= KN; ++r2) {
            unsigned long long h =
                (lane < WPQ) ? lists[q][lane][pos] : ~0ULL;
            unsigned long long w = warp_min_u64(h);
            if (h == w && lane < WPQ) ++pos;  // unique keys -> one owner
            if (lane == 0 && r2 > 0)
                g_knn[(size_t)(g0 + q) * KN + (r2 - 1)] =
                    (int)(w & 0xffffffffu);
        }
    }
}

// ---------------------------------------------------------------------------
// Stage B dense layer: 512 threads, 16 groups. Thread t computes output
// j=t&255 for the 8 groups of set t>>8. Weights staged [j][i] stride 20
// (float4 reads: lane*5 mod 8 -> conflict-free), inputs broadcast float4.
// ---------------------------------------------------------------------------
__device__ __forceinline__ void dense_layer(
    int IN, int instride, const float* inp, float* outp,
    const float* __restrict__ W, const float* __restrict__ bias,
    const float* __restrict__ gam, const float* __restrict__ bet,
    float* wstage, bool do_relu, bool transp, int tid)
{
    int j = tid & 255;
    int gset = tid >> 8;
    const float* inb = inp + gset * 8 * instride;
    float acc[8];
#pragma unroll
    for (int g = 0; g < 8; ++g) acc[g] = 0.f;

    for (int i0 = 0; i0 < IN; i0 += 16) {
#pragma unroll
        for (int p = 0; p < 2; ++p) {
            int t4 = tid + p * TPB;            // < 1024
            int row = t4 >> 2;
            int iv = (t4 & 3) * 4;
            float4 w4 = *(const float4*)(W + (size_t)row * IN + i0 + iv);
            *(float4*)(wstage + row * 20 + iv) = w4;
        }
        __syncthreads();
        const float* wr = wstage + j * 20;
#pragma unroll
        for (int i = 0; i < 16; i += 4) {
            float4 w4 = *(const float4*)(wr + i);
#pragma unroll
            for (int g = 0; g < 8; ++g) {
                float4 h4 = *(const float4*)(inb + g * instride + i0 + i);
                acc[g] = fmaf(h4.x, w4.x, acc[g]);
                acc[g] = fmaf(h4.y, w4.y, acc[g]);
                acc[g] = fmaf(h4.z, w4.z, acc[g]);
                acc[g] = fmaf(h4.w, w4.w, acc[g]);
            }
        }
        __syncthreads();
    }
    float bj = bias[j], gj = gam[j], btj = bet[j];
    int oidx = transp ? (((j & 15) << 4) | (j >> 4)) : j;
    float* outb = outp + gset * 8 * K2F;
#pragma unroll
    for (int g = 0; g < 8; ++g) {
        float v = fmaf(acc[g] + bj, gj, btj);
        if (do_relu) v = fmaxf(v, 0.f);
        outb[g * K2F + oidx] = v;
    }
    __syncthreads();
}

// ---------------------------------------------------------------------------
// Stage B: 16 groups per block, 512 threads, 256 blocks. h2 aliases the Tf
// buffer; Tf+conv processed in two 8-group halves; smem ~100KB (2 CTAs/SM).
// Conv weights staged [o][q] stride 68 -> one float4 LDS per 4 q-steps.
// ---------------------------------------------------------------------------
__global__ void __launch_bounds__(TPB, 2) group_kernel(
    const float* __restrict__ points, const float* __restrict__ features,
    const float* __restrict__ lift_w, const float* __restrict__ lift_b,
    const float* __restrict__ bnl_g, const float* __restrict__ bnl_b,
    const float* __restrict__ t1_w, const float* __restrict__ t1_b,
    const float* __restrict__ bn1_g, const float* __restrict__ bn1_b,
    const float* __restrict__ t2_w, const float* __restrict__ t2_b,
    const float* __restrict__ bn2_g, const float* __restrict__ bn2_b,
    const float* __restrict__ t3_w, const float* __restrict__ t3_b,
    const float* __restrict__ bn3_g, const float* __restrict__ bn3_b,
    const float* __restrict__ conv_w, const float* __restrict__ conv_b,
    const int* __restrict__ rep_idx,
    float* __restrict__ out_rep, float* __restrict__ out_main)
{
    extern __shared__ float sm[];
    float* p_s    = sm;                      // 16*48   = 768
    float* hA     = p_s + GPB * 48;          // 16*256  = 4096
    float* TfB    = hA + GPB * K2F;          // 8*1280  = 10240 (hB aliases)
    float* hB     = TfB;                     // 16*256  = 4096 (dead before Tf)
    float* feat   = TfB + 8 * 1280;          // 16*80   = 1280
    float* wstage = feat + 16 * 80;          // 8704 (conv 128*68; dense 256*20)
    float* liftp  = wstage + 8704;           // 96
    int*   nb_s   = (int*)(liftp + 96);      // 16*16 ints

    int tid  = threadIdx.x;
    int gblk = blockIdx.x * GPB;
    int bb   = gblk >> 11;

    if (tid < 48) liftp[tid] = lift_w[tid];
    else if (tid < 64) {
        int c = tid - 48;
        liftp[48 + c] = lift_b[c];
        liftp[64 + c] = bnl_g[c];
        liftp[80 + c] = bnl_b[c];
    }
    if (tid < 256) {
        int g = tid >> 4, k = tid & 15;
        int gg = gblk + g;
        int r = gg & (RQ - 1);
        int ri = rep_idx[r];
        const float* rp = points + ((size_t)bb * NPTS + ri) * 3;
        float rx = rp[0], ry = rp[1], rz = rp[2];
        int nb = g_knn[(size_t)gg * KN + k];
        nb_s[g * 16 + k] = nb;
        const float* np = points + ((size_t)bb * NPTS + nb) * 3;
        p_s[g * 48 + k * 3 + 0] = np[0] - rx;
        p_s[g * 48 + k * 3 + 1] = np[1] - ry;
        p_s[g * 48 + k * 3 + 2] = np[2] - rz;
        if (k == 0) {
            out_rep[(size_t)gg * 3 + 0] = rx;
            out_rep[(size_t)gg * 3 + 1] = ry;
            out_rep[(size_t)gg * 3 + 2] = rz;
        }
    }
    __syncthreads();

    dense_layer(48, 48,   p_s, hA, t1_w, t1_b, bn1_g, bn1_b, wstage, true,  false, tid);
    dense_layer(256, 256, hA,  hB, t2_w, t2_b, bn2_g, bn2_b, wstage, true,  false, tid);
    dense_layer(256, 256, hB,  hA, t3_w, t3_b, bn3_g, bn3_b, wstage, false, true,  tid);
    // hA holds Tt[g][j*16+k] = T[k][j] for all 16 groups

    int o = tid & 127, gh = tid >> 7;        // gh in 0..3 -> 2 groups each

    for (int half = 0; half < 2; ++half) {
        // build Tf for 8 groups of this half
        for (int g8 = 0; g8 < 8; ++g8) {
            int gg = half * 8 + g8;
            for (int t = tid; t < 16 * CINF; t += TPB) {
                int k = t >> 6, c = t & 63;
                feat[k * 80 + 16 + c] =
                    features[((size_t)bb * NPTS + nb_s[gg * 16 + k]) * CINF + c];
            }
            if (tid < 256) {
                int k = tid >> 4, cl = tid & 15;
                const float* pr = p_s + gg * 48 + k * 3;
                float a = fmaf(pr[0], liftp[cl * 3 + 0],
                          fmaf(pr[1], liftp[cl * 3 + 1], pr[2] * liftp[cl * 3 + 2]));
                float v = fmaf(a + liftp[48 + cl], liftp[64 + cl], liftp[80 + cl]);
                feat[k * 80 + cl] = fmaxf(v, 0.f);
            }
            __syncthreads();
            const float* Tt = hA + gg * K2F;
            for (int t = tid; t < 1280; t += TPB) {
                int k = t & 15, c = t >> 4;
                float s = 0.f;
#pragma unroll
                for (int j = 0; j < 16; ++j)
                    s = fmaf(Tt[j * 16 + k], feat[j * 80 + c], s);
                TfB[g8 * 1280 + t] = s;      // q = c*16+k == t
            }
            __syncthreads();
        }

        // conv over this half's 8 groups; weights staged [o][q] stride 68
        float cacc0 = 0.f, cacc1 = 0.f;
        for (int q0 = 0; q0 < 1280; q0 += 64) {
#pragma unroll
            for (int p = 0; p < 4; ++p) {
                int t4 = tid + p * TPB;       // < 2048
                int oo = t4 >> 4;
                int qv = (t4 & 15) * 4;
                float4 w4 = *(const float4*)(conv_w + (size_t)oo * 1280 + q0 + qv);
                *(float4*)(wstage + oo * 68 + qv) = w4;
            }
            __syncthreads();
            const float* wr  = wstage + o * 68;
            const float* tf0 = TfB + (gh * 2 + 0) * 1280 + q0;
            const float* tf1 = tf0 + 1280;
#pragma unroll
            for (int qq = 0; qq < 64; qq += 4) {
                float4 w4 = *(const float4*)(wr + qq);
                float4 a  = *(const float4*)(tf0 + qq);
                float4 b4 = *(const float4*)(tf1 + qq);
                cacc0 = fmaf(a.x, w4.x, cacc0);
                cacc0 = fmaf(a.y, w4.y, cacc0);
                cacc0 = fmaf(a.z, w4.z, cacc0);
                cacc0 = fmaf(a.w, w4.w, cacc0);
                cacc1 = fmaf(b4.x, w4.x, cacc1);
                cacc1 = fmaf(b4.y, w4.y, cacc1);
                cacc1 = fmaf(b4.z, w4.z, cacc1);
                cacc1 = fmaf(b4.w, w4.w, cacc1);
            }
            __syncthreads();
        }
        float cb = conv_b[o];
        int gbase = gblk + half * 8 + gh * 2;
        out_main[(size_t)(gbase + 0) * COUTF + o] = cacc0 + cb;
        out_main[(size_t)(gbase + 1) * COUTF + o] = cacc1 + cb;
    }
}

// ---------------------------------------------------------------------------
extern "C" void kernel_launch(void* const* d_in, const int* in_sizes, int n_in,
                              void* d_out, int out_size)
{
    const float* points  = (const float*)d_in[0];
    const float* feats   = (const float*)d_in[1];
    const float* lift_w  = (const float*)d_in[2];
    const float* lift_b  = (const float*)d_in[3];
    const float* bnl_g   = (const float*)d_in[4];
    const float* bnl_b   = (const float*)d_in[5];
    const float* t1_w    = (const float*)d_in[6];
    const float* t1_b    = (const float*)d_in[7];
    const float* bn1_g   = (const float*)d_in[8];
    const float* bn1_b   = (const float*)d_in[9];
    const float* t2_w    = (const float*)d_in[10];
    const float* t2_b    = (const float*)d_in[11];
    const float* bn2_g   = (const float*)d_in[12];
    const float* bn2_b   = (const float*)d_in[13];
    const float* t3_w    = (const float*)d_in[14];
    const float* t3_b    = (const float*)d_in[15];
    const float* bn3_g   = (const float*)d_in[16];
    const float* bn3_b   = (const float*)d_in[17];
    const float* conv_w  = (const float*)d_in[18];
    const float* conv_b  = (const float*)d_in[19];
    const int*   rep_idx = (const int*)d_in[20];

    float* out_rep  = (float*)d_out;                 // (B, R, 3) first
    float* out_main = out_rep + (size_t)BR * 3;      // then (B, R, 128)

    size_t smemB = (size_t)(GPB * 48 + GPB * K2F + 8 * 1280 + 16 * 80 +
                            8704 + 96 + GPB * 16) * sizeof(float);

    cudaFuncSetAttribute(group_kernel, cudaFuncAttributeMaxDynamicSharedMemorySize,
                         (int)smemB);

    knn_kernel<<<BR / 2, 512>>>(points, rep_idx);
    group_kernel<<<BR / GPB, TPB, smemB>>>(
        points, feats, lift_w, lift_b, bnl_g, bnl_b,
        t1_w, t1_b, bn1_g, bn1_b, t2_w, t2_b, bn2_g, bn2_b,
        t3_w, t3_b, bn3_g, bn3_b, conv_w, conv_b, rep_idx,
        out_rep, out_main);
}

// round 17
// speedup vs baseline: 2.0218x; 2.0218x over previous
#include <cuda_runtime.h>
#include <cstdint>

// Problem constants
#define BATCH 2
#define NPTS  8192
#define RQ    2048
#define KN    16     // neighbors kept
#define BR    4096   // BATCH*RQ groups
#define CINF  64
#define COUTF 128
#define K2F   256
#define GPB   16     // groups per block in stage B
#define TPB   512    // threads per block in stage B
#define NPART 2      // candidate partitions per query
#define CPP   (NPTS / NPART)   // candidates per part = 4096

// Scratch
__device__ int g_knn[BR * KN];
__device__ unsigned long long g_part[BR * NPART * (KN + 1)];

__device__ __forceinline__ unsigned fkey(float f) {
    unsigned u = __float_as_uint(f);
    return (u & 0x80000000u) ? ~u : (u | 0x80000000u);
}

// ---------------------------------------------------------------------------
// Stage A1: partial exact KNN, tournament selection (R10 configuration —
// best measured). One block = 2 queries (warp-halves) x 1 partition of 4096.
// d2 arithmetic bit-identical: dot = FMA chain, sq = plain mul+add,
// combine unfused. Each thread memoizes the min u64 key of its 32
// candidates; per pass one atomicMin + one named barrier; only the winner
// rescans with prev = winner. Extraction order == jax top_k w/ tie-break.
// ---------------------------------------------------------------------------
__global__ void __launch_bounds__(256, 6) knn_part_kernel(
    const float* __restrict__ points, const int* __restrict__ rep_idx)
{
    extern __shared__ unsigned smA[];
    unsigned* keys = smA;                                  // 2*4096 u32
    unsigned long long* slots =
        (unsigned long long*)(smA + 2 * CPP);              // 2*17 u64

    int tid  = threadIdx.x;
    int part = blockIdx.x & (NPART - 1);
    int g0   = (blockIdx.x >> 1) * 2;
    int b    = g0 >> 11;
    int j0   = part * CPP;

    float qx[2], qy[2], qz[2], qs[2];
#pragma unroll
    for (int s = 0; s < 2; ++s) {
        int r = (g0 + s) & (RQ - 1);
        int ri = rep_idx[r];
        const float* pp = points + ((size_t)b * NPTS + ri) * 3;
        float x = pp[0], y = pp[1], z = pp[2];
        qx[s] = x; qy[s] = y; qz[s] = z;
        qs[s] = __fadd_rn(__fadd_rn(__fmul_rn(x, x), __fmul_rn(y, y)), __fmul_rn(z, z));
    }

    if (tid < 2 * (KN + 1)) slots[tid] = ~0ULL;

    for (int jj = tid; jj < CPP; jj += 256) {
        const float* pp = points + ((size_t)b * NPTS + j0 + jj) * 3;
        float x = pp[0], y = pp[1], z = pp[2];
        float sj = __fadd_rn(__fadd_rn(__fmul_rn(x, x), __fmul_rn(y, y)), __fmul_rn(z, z));
#pragma unroll
        for (int s = 0; s < 2; ++s) {
            float dot = __fmaf_rn(qz[s], z,
                        __fmaf_rn(qy[s], y,
                        __fmul_rn(qx[s], x)));
            float d2 = __fsub_rn(__fadd_rn(qs[s], sj), __fmul_rn(2.0f, dot));
            keys[s * CPP + jj] = fkey(d2);
        }
    }
    __syncthreads();

    int s  = tid >> 7;               // query handled by this half
    int lt = tid & 127;
    const unsigned* kk = keys + s * CPP;
    unsigned long long* slot = slots + s * (KN + 1);

    // scan this thread's 32 candidates for the min u64 key strictly > prev
    auto scan = [&](unsigned long long prev) -> unsigned long long {
        unsigned long long best = ~0ULL;
#pragma unroll
        for (int c = 0; c < 8; ++c) {
            int jj = c * 512 + lt * 4;
            uint4 v = *(const uint4*)(kk + jj);
            unsigned base = (unsigned)(j0 + jj);
            unsigned long long k0 = ((unsigned long long)v.x << 32) | (base + 0);
            unsigned long long k1 = ((unsigned long long)v.y << 32) | (base + 1);
            unsigned long long k2 = ((unsigned long long)v.z << 32) | (base + 2);
            unsigned long long k3 = ((unsigned long long)v.w << 32) | (base + 3);
            if (k0 > prev && k0 < best) best = k0;
            if (k1 > prev && k1 < best) best = k1;
            if (k2 > prev && k2 < best) best = k2;
            if (k3 > prev && k3 < best) best = k3;
        }
        return best;
    };

    unsigned long long local_best = scan(0ULL);

    for (int it = 0; it <= KN; ++it) {
        atomicMin(&slot[it], local_best);
        asm volatile("bar.sync %0, %1;" :: "r"(s + 1), "r"(128) : "memory");
        unsigned long long w = slot[it];
        if (lt == 0)
            g_part[((size_t)(g0 + s) * NPART + part) * (KN + 1) + it] = w;
        if (local_best == w) local_best = scan(w);   // only the winner rescans
    }
}

// ---------------------------------------------------------------------------
// Stage A2: merge the NPART sorted top-17 lists per query, drop entry 0
// (the reference drops idx[...,0]), keep neighbors 1..16.
// ---------------------------------------------------------------------------
__global__ void __launch_bounds__(256) knn_merge_kernel()
{
    int g = blockIdx.x * 256 + threadIdx.x;
    if (g >= BR) return;
    const unsigned long long* A = g_part + (size_t)g * NPART * (KN + 1);
    const unsigned long long* Bl = A + (KN + 1);
    int ia = 0, ib = 0;
    for (int r = 0; r <= KN; ++r) {
        unsigned long long a = A[ia], bk = Bl[ib];
        unsigned long long m;
        if (a < bk) { m = a; ++ia; } else { m = bk; ++ib; }
        if (r > 0) g_knn[(size_t)g * KN + (r - 1)] = (int)(m & 0xffffffffu);
    }
}

// ---------------------------------------------------------------------------
// Stage B dense layer: 512 threads, 16 groups. Thread t computes TWO outputs
// j = s and s+128 (s = t&127) for the FOUR groups of set t>>7 — 6 LDS.128
// per 32 FMA (was 9). Weight reads at stride 20 stay conflict-free at both
// j offsets (lane*5 mod 8 covers all banks); input reads are warp-broadcast.
// Per-output accumulation order identical to previous version.
// ---------------------------------------------------------------------------
__device__ __forceinline__ void dense_layer(
    int IN, int instride, const float* inp, float* outp,
    const float* __restrict__ W, const float* __restrict__ bias,
    const float* __restrict__ gam, const float* __restrict__ bet,
    float* wstage, bool do_relu, bool transp, int tid)
{
    int s = tid & 127;                 // output slot: j = s, s+128
    int gset = tid >> 7;               // groups gset*4 .. gset*4+3
    const float* inb = inp + gset * 4 * instride;
    float acc0[4], acc1[4];
#pragma unroll
    for (int g = 0; g < 4; ++g) { acc0[g] = 0.f; acc1[g] = 0.f; }

    for (int i0 = 0; i0 < IN; i0 += 16) {
#pragma unroll
        for (int p = 0; p < 2; ++p) {
            int t4 = tid + p * TPB;            // < 1024
            int row = t4 >> 2;
            int iv = (t4 & 3) * 4;
            float4 w4 = *(const float4*)(W + (size_t)row * IN + i0 + iv);
            *(float4*)(wstage + row * 20 + iv) = w4;
        }
        __syncthreads();
        const float* wr0 = wstage + s * 20;
        const float* wr1 = wstage + (s + 128) * 20;
#pragma unroll
        for (int i = 0; i < 16; i += 4) {
            float4 wa = *(const float4*)(wr0 + i);
            float4 wb = *(const float4*)(wr1 + i);
#pragma unroll
            for (int g = 0; g < 4; ++g) {
                float4 h4 = *(const float4*)(inb + g * instride + i0 + i);
                acc0[g] = fmaf(h4.x, wa.x, acc0[g]);
                acc0[g] = fmaf(h4.y, wa.y, acc0[g]);
                acc0[g] = fmaf(h4.z, wa.z, acc0[g]);
                acc0[g] = fmaf(h4.w, wa.w, acc0[g]);
                acc1[g] = fmaf(h4.x, wb.x, acc1[g]);
                acc1[g] = fmaf(h4.y, wb.y, acc1[g]);
                acc1[g] = fmaf(h4.z, wb.z, acc1[g]);
                acc1[g] = fmaf(h4.w, wb.w, acc1[g]);
            }
        }
        __syncthreads();
    }
    float* outb = outp + gset * 4 * K2F;
#pragma unroll
    for (int jj = 0; jj < 2; ++jj) {
        int j = s + jj * 128;
        float bj = bias[j], gj = gam[j], btj = bet[j];
        int oidx = transp ? (((j & 15) << 4) | (j >> 4)) : j;
        const float* ac = jj ? acc1 : acc0;
#pragma unroll
        for (int g = 0; g < 4; ++g) {
            float v = fmaf(ac[g] + bj, gj, btj);
            if (do_relu) v = fmaxf(v, 0.f);
            outb[g * K2F + oidx] = v;
        }
    }
    __syncthreads();
}

// ---------------------------------------------------------------------------
// Stage B: 16 groups per block, 512 threads, 256 blocks. h2 aliases the Tf
// buffer; Tf+conv processed in two 8-group halves; smem ~100KB (2 CTAs/SM).
// Conv weights staged [o][q] stride 68 -> one float4 LDS per 4 q-steps.
// ---------------------------------------------------------------------------
__global__ void __launch_bounds__(TPB, 2) group_kernel(
    const float* __restrict__ points, const float* __restrict__ features,
    const float* __restrict__ lift_w, const float* __restrict__ lift_b,
    const float* __restrict__ bnl_g, const float* __restrict__ bnl_b,
    const float* __restrict__ t1_w, const float* __restrict__ t1_b,
    const float* __restrict__ bn1_g, const float* __restrict__ bn1_b,
    const float* __restrict__ t2_w, const float* __restrict__ t2_b,
    const float* __restrict__ bn2_g, const float* __restrict__ bn2_b,
    const float* __restrict__ t3_w, const float* __restrict__ t3_b,
    const float* __restrict__ bn3_g, const float* __restrict__ bn3_b,
    const float* __restrict__ conv_w, const float* __restrict__ conv_b,
    const int* __restrict__ rep_idx,
    float* __restrict__ out_rep, float* __restrict__ out_main)
{
    extern __shared__ float sm[];
    float* p_s    = sm;                      // 16*48   = 768
    float* hA     = p_s + GPB * 48;          // 16*256  = 4096
    float* TfB    = hA + GPB * K2F;          // 8*1280  = 10240 (hB aliases)
    float* hB     = TfB;                     // 16*256  = 4096 (dead before Tf)
    float* feat   = TfB + 8 * 1280;          // 16*80   = 1280
    float* wstage = feat + 16 * 80;          // 8704 (conv 128*68; dense 256*20)
    float* liftp  = wstage + 8704;           // 96
    int*   nb_s   = (int*)(liftp + 96);      // 16*16 ints

    int tid  = threadIdx.x;
    int gblk = blockIdx.x * GPB;
    int bb   = gblk >> 11;

    if (tid < 48) liftp[tid] = lift_w[tid];
    else if (tid < 64) {
        int c = tid - 48;
        liftp[48 + c] = lift_b[c];
        liftp[64 + c] = bnl_g[c];
        liftp[80 + c] = bnl_b[c];
    }
    if (tid < 256) {
        int g = tid >> 4, k = tid & 15;
        int gg = gblk + g;
        int r = gg & (RQ - 1);
        int ri = rep_idx[r];
        const float* rp = points + ((size_t)bb * NPTS + ri) * 3;
        float rx = rp[0], ry = rp[1], rz = rp[2];
        int nb = g_knn[(size_t)gg * KN + k];
        nb_s[g * 16 + k] = nb;
        const float* np = points + ((size_t)bb * NPTS + nb) * 3;
        p_s[g * 48 + k * 3 + 0] = np[0] - rx;
        p_s[g * 48 + k * 3 + 1] = np[1] - ry;
        p_s[g * 48 + k * 3 + 2] = np[2] - rz;
        if (k == 0) {
            out_rep[(size_t)gg * 3 + 0] = rx;
            out_rep[(size_t)gg * 3 + 1] = ry;
            out_rep[(size_t)gg * 3 + 2] = rz;
        }
    }
    __syncthreads();

    dense_layer(48, 48,   p_s, hA, t1_w, t1_b, bn1_g, bn1_b, wstage, true,  false, tid);
    dense_layer(256, 256, hA,  hB, t2_w, t2_b, bn2_g, bn2_b, wstage, true,  false, tid);
    dense_layer(256, 256, hB,  hA, t3_w, t3_b, bn3_g, bn3_b, wstage, false, true,  tid);
    // hA holds Tt[g][j*16+k] = T[k][j] for all 16 groups

    int o = tid & 127, gh = tid >> 7;        // gh in 0..3 -> 2 groups each

    for (int half = 0; half < 2; ++half) {
        // build Tf for 8 groups of this half
        for (int g8 = 0; g8 < 8; ++g8) {
            int gg = half * 8 + g8;
            for (int t = tid; t < 16 * CINF; t += TPB) {
                int k = t >> 6, c = t & 63;
                feat[k * 80 + 16 + c] =
                    features[((size_t)bb * NPTS + nb_s[gg * 16 + k]) * CINF + c];
            }
            if (tid < 256) {
                int k = tid >> 4, cl = tid & 15;
                const float* pr = p_s + gg * 48 + k * 3;
                float a = fmaf(pr[0], liftp[cl * 3 + 0],
                          fmaf(pr[1], liftp[cl * 3 + 1], pr[2] * liftp[cl * 3 + 2]));
                float v = fmaf(a + liftp[48 + cl], liftp[64 + cl], liftp[80 + cl]);
                feat[k * 80 + cl] = fmaxf(v, 0.f);
            }
            __syncthreads();
            const float* Tt = hA + gg * K2F;
            for (int t = tid; t < 1280; t += TPB) {
                int k = t & 15, c = t >> 4;
                float s = 0.f;
#pragma unroll
                for (int j = 0; j < 16; ++j)
                    s = fmaf(Tt[j * 16 + k], feat[j * 80 + c], s);
                TfB[g8 * 1280 + t] = s;      // q = c*16+k == t
            }
            __syncthreads();
        }

        // conv over this half's 8 groups; weights staged [o][q] stride 68
        float cacc0 = 0.f, cacc1 = 0.f;
        for (int q0 = 0; q0 < 1280; q0 += 64) {
#pragma unroll
            for (int p = 0; p < 4; ++p) {
                int t4 = tid + p * TPB;       // < 2048
                int oo = t4 >> 4;
                int qv = (t4 & 15) * 4;
                float4 w4 = *(const float4*)(conv_w + (size_t)oo * 1280 + q0 + qv);
                *(float4*)(wstage + oo * 68 + qv) = w4;
            }
            __syncthreads();
            const float* wr  = wstage + o * 68;
            const float* tf0 = TfB + (gh * 2 + 0) * 1280 + q0;
            const float* tf1 = tf0 + 1280;
#pragma unroll
            for (int qq = 0; qq < 64; qq += 4) {
                float4 w4 = *(const float4*)(wr + qq);
                float4 a  = *(const float4*)(tf0 + qq);
                float4 b4 = *(const float4*)(tf1 + qq);
                cacc0 = fmaf(a.x, w4.x, cacc0);
                cacc0 = fmaf(a.y, w4.y, cacc0);
                cacc0 = fmaf(a.z, w4.z, cacc0);
                cacc0 = fmaf(a.w, w4.w, cacc0);
                cacc1 = fmaf(b4.x, w4.x, cacc1);
                cacc1 = fmaf(b4.y, w4.y, cacc1);
                cacc1 = fmaf(b4.z, w4.z, cacc1);
                cacc1 = fmaf(b4.w, w4.w, cacc1);
            }
            __syncthreads();
        }
        float cb = conv_b[o];
        int gbase = gblk + half * 8 + gh * 2;
        out_main[(size_t)(gbase + 0) * COUTF + o] = cacc0 + cb;
        out_main[(size_t)(gbase + 1) * COUTF + o] = cacc1 + cb;
    }
}

// ---------------------------------------------------------------------------
extern "C" void kernel_launch(void* const* d_in, const int* in_sizes, int n_in,
                              void* d_out, int out_size)
{
    const float* points  = (const float*)d_in[0];
    const float* feats   = (const float*)d_in[1];
    const float* lift_w  = (const float*)d_in[2];
    const float* lift_b  = (const float*)d_in[3];
    const float* bnl_g   = (const float*)d_in[4];
    const float* bnl_b   = (const float*)d_in[5];
    const float* t1_w    = (const float*)d_in[6];
    const float* t1_b    = (const float*)d_in[7];
    const float* bn1_g   = (const float*)d_in[8];
    const float* bn1_b   = (const float*)d_in[9];
    const float* t2_w    = (const float*)d_in[10];
    const float* t2_b    = (const float*)d_in[11];
    const float* bn2_g   = (const float*)d_in[12];
    const float* bn2_b   = (const float*)d_in[13];
    const float* t3_w    = (const float*)d_in[14];
    const float* t3_b    = (const float*)d_in[15];
    const float* bn3_g   = (const float*)d_in[16];
    const float* bn3_b   = (const float*)d_in[17];
    const float* conv_w  = (const float*)d_in[18];
    const float* conv_b  = (const float*)d_in[19];
    const int*   rep_idx = (const int*)d_in[20];

    float* out_rep  = (float*)d_out;                 // (B, R, 3) first
    float* out_main = out_rep + (size_t)BR * 3;      // then (B, R, 128)

    size_t smemP = (size_t)2 * CPP * sizeof(unsigned) +
                   2 * (KN + 1) * sizeof(unsigned long long);
    size_t smemB = (size_t)(GPB * 48 + GPB * K2F + 8 * 1280 + 16 * 80 +
                            8704 + 96 + GPB * 16) * sizeof(float);

    cudaFuncSetAttribute(knn_part_kernel, cudaFuncAttributeMaxDynamicSharedMemorySize,
                         (int)smemP);
    cudaFuncSetAttribute(group_kernel, cudaFuncAttributeMaxDynamicSharedMemorySize,
                         (int)smemB);

    knn_part_kernel<<<BR, 256, smemP>>>(points, rep_idx);
    knn_merge_kernel<<<BR / 256, 256>>>();
    group_kernel<<<BR / GPB, TPB, smemB>>>(
        points, feats, lift_w, lift_b, bnl_g, bnl_b,
        t1_w, t1_b, bn1_g, bn1_b, t2_w, t2_b, bn2_g, bn2_b,
        t3_w, t3_b, bn3_g, bn3_b, conv_w, conv_b, rep_idx,
        out_rep, out_main);
}